// round 11
// baseline (speedup 1.0000x reference)
#include <cuda_runtime.h>
#include <cuda_bf16.h>
#include <cstdint>

// LinearAttentionTriton (all-HMMA):
//   g_part_t[e*64+d] = M_t[d][e] = sum_r K[r][d] V[r][e]   -- kA (mma.sync bf16 hi/lo)
//   g_S[e*64+c]      = S[c][e],  S = sum_t M_t^T           -- kB1/kB2 (deterministic)
//   out_t = (Q_t @ M_t) @ S                                 -- kQO (mma.sync bf16 hi/lo)
// N = 262144, D = 64, TRUNK = 128, T = 2048.

#define D 64
#define TRUNK 128
#define T_TRUNKS 2048
#define B1_BLOCKS 256

__device__ __align__(16) float g_S[D * D];
__device__ __align__(16) float g_part[T_TRUNKS * D * D];
__device__ __align__(16) float g_red[B1_BLOCKS * D * D];

// ---------------- common helpers ----------------
__device__ __forceinline__ uint32_t smem_u32(const void* p) {
    uint32_t a;
    asm("{ .reg .u64 t; cvta.to.shared.u64 t, %1; cvt.u32.u64 %0, t; }"
        : "=r"(a) : "l"(p));
    return a;
}
#define LDSM_X4(r0, r1, r2, r3, a) \
    asm volatile("ldmatrix.sync.aligned.m8n8.x4.shared.b16 {%0,%1,%2,%3}, [%4];" \
                 : "=r"(r0), "=r"(r1), "=r"(r2), "=r"(r3) : "r"(a))
#define LDSM_X2(r0, r1, a) \
    asm volatile("ldmatrix.sync.aligned.m8n8.x2.shared.b16 {%0,%1}, [%2];" \
                 : "=r"(r0), "=r"(r1) : "r"(a))
#define LDSM_X4_T(r0, r1, r2, r3, a) \
    asm volatile("ldmatrix.sync.aligned.m8n8.x4.trans.shared.b16 {%0,%1,%2,%3}, [%4];" \
                 : "=r"(r0), "=r"(r1), "=r"(r2), "=r"(r3) : "r"(a))
#define LDSM_X2_T(r0, r1, a) \
    asm volatile("ldmatrix.sync.aligned.m8n8.x2.trans.shared.b16 {%0,%1}, [%2];" \
                 : "=r"(r0), "=r"(r1) : "r"(a))
#define MMA16816(d, a, b) \
    asm volatile("mma.sync.aligned.m16n8k16.row.col.f32.bf16.bf16.f32 " \
                 "{%0,%1,%2,%3}, {%4,%5,%6,%7}, {%8,%9}, {%0,%1,%2,%3};" \
                 : "+f"((d)[0]), "+f"((d)[1]), "+f"((d)[2]), "+f"((d)[3]) \
                 : "r"((a)[0]), "r"((a)[1]), "r"((a)[2]), "r"((a)[3]), \
                   "r"((b)[0]), "r"((b)[1]))

__device__ __forceinline__ void split_pair(char* ph, char* pl, float x, float y) {
    __nv_bfloat16 hx = __float2bfloat16_rn(x), hy = __float2bfloat16_rn(y);
    __nv_bfloat162 h; h.x = hx; h.y = hy;
    __nv_bfloat162 l;
    l.x = __float2bfloat16_rn(x - __bfloat162float(hx));
    l.y = __float2bfloat16_rn(y - __bfloat162float(hy));
    *(__nv_bfloat162*)ph = h;
    *(__nv_bfloat162*)pl = l;
}

// ---------------- kA: M^T via mma.sync (256 thr, 4 m-tiles x 2 k-halves) ----------------
// out[m=e][n=d] = sum_r V[r][e] K[r][d]  (A = V^T, B = K^T; K,V stored natural [r][.])
// smem: Kh, Kl, Vh, Vl each [128][72] bf16. 72 KB -> 3 CTAs/SM (24 warps).
#define KA_STRB 144
#define KA_KH 0
#define KA_KL 18432
#define KA_VH 36864
#define KA_VL 55296
#define KA_SMEM 73728
#define PARK_STR 68          // floats per park row (conflict-free)
#define PARK_TILE (16 * PARK_STR)

__global__ void __launch_bounds__(256) kA(const float* __restrict__ Kg,
                                          const float* __restrict__ Vg) {
    extern __shared__ __align__(16) char sm[];
    const uint32_t sb = smem_u32(sm);
    const int tid = threadIdx.x, lane = tid & 31, wid = tid >> 5;
    const long t = blockIdx.x;

    const float4* K4 = (const float4*)Kg + t * 2048;
    const float4* V4 = (const float4*)Vg + t * 2048;
#pragma unroll
    for (int i = tid; i < 2048; i += 256) {
        const int off = (i >> 4) * KA_STRB + ((i & 15) << 3);  // row*144 + col*2
        const float4 kv = K4[i];
        split_pair(sm + KA_KH + off,     sm + KA_KL + off,     kv.x, kv.y);
        split_pair(sm + KA_KH + off + 4, sm + KA_KL + off + 4, kv.z, kv.w);
        const float4 vv = V4[i];
        split_pair(sm + KA_VH + off,     sm + KA_VL + off,     vv.x, vv.y);
        split_pair(sm + KA_VH + off + 4, sm + KA_VL + off + 4, vv.z, vv.w);
    }
    __syncthreads();

    const int mt = wid & 3;          // m-tile (rows e = mt*16..+16)
    const int kh = wid >> 2;         // k-half (rows r = kh*64..+64)
    const int m0 = mt * 16;

    float acc[8][4];
#pragma unroll
    for (int n = 0; n < 8; ++n)
#pragma unroll
        for (int j = 0; j < 4; ++j) acc[n][j] = 0.0f;

    // A (trans x4): lane l -> &V[k + (l&7) + ((l>>4)<<3)][m0 + ((l>>3)&1)*8]
    const uint32_t aBase = sb + KA_VH
        + (uint32_t)((kh * 64 + (lane & 7) + ((lane >> 4) << 3)) * KA_STRB)
        + (uint32_t)((m0 + ((lane >> 3) & 1) * 8) * 2);
    // B (trans x2): lane l (0-15) -> &K[k + (l&7) + ((l>>3)&1)*8][n0]
    const uint32_t bBase = sb + KA_KH
        + (uint32_t)((kh * 64 + (lane & 7) + ((lane >> 3) & 1) * 8) * KA_STRB);

#pragma unroll
    for (int k0 = 0; k0 < 64; k0 += 16) {
        uint32_t ah[4], al[4];
        const uint32_t aa = aBase + (uint32_t)(k0 * KA_STRB);
        LDSM_X4_T(ah[0], ah[1], ah[2], ah[3], aa);
        LDSM_X4_T(al[0], al[1], al[2], al[3], aa + (KA_VL - KA_VH));
#pragma unroll
        for (int n = 0; n < 8; ++n) {
            uint32_t bh[2], bl[2];
            const uint32_t ba = bBase + (uint32_t)(k0 * KA_STRB) + (uint32_t)(n * 16);
            LDSM_X2_T(bh[0], bh[1], ba);
            LDSM_X2_T(bl[0], bl[1], ba + (KA_KL - KA_KH));
            MMA16816(acc[n], ah, bh);
            MMA16816(acc[n], ah, bl);
            MMA16816(acc[n], al, bh);
        }
    }
    __syncthreads();   // all smem reads done; reuse KA_KH region as park

    float* park = (float*)sm;        // 4 tiles * 16 * PARK_STR floats = 17408 B
    const int g = lane >> 2, tc = lane & 3;
    if (kh == 1) {
#pragma unroll
        for (int n = 0; n < 8; ++n) {
            const int col = n * 8 + tc * 2;
            float2 v0; v0.x = acc[n][0]; v0.y = acc[n][1];
            float2 v1; v1.x = acc[n][2]; v1.y = acc[n][3];
            *(float2*)&park[mt * PARK_TILE + g * PARK_STR + col]       = v0;
            *(float2*)&park[mt * PARK_TILE + (g + 8) * PARK_STR + col] = v1;
        }
    }
    __syncthreads();
    if (kh == 0) {
        float* dst = g_part + t * 4096;
#pragma unroll
        for (int n = 0; n < 8; ++n) {
            const int col = n * 8 + tc * 2;
            const float2 p0 = *(const float2*)&park[mt * PARK_TILE + g * PARK_STR + col];
            const float2 p1 = *(const float2*)&park[mt * PARK_TILE + (g + 8) * PARK_STR + col];
            float2 v0; v0.x = acc[n][0] + p0.x; v0.y = acc[n][1] + p0.y;
            float2 v1; v1.x = acc[n][2] + p1.x; v1.y = acc[n][3] + p1.y;
            *(float2*)&dst[(m0 + g) * 64 + col]     = v0;
            *(float2*)&dst[(m0 + g + 8) * 64 + col] = v1;
        }
    }
}

// ---------------- kB1/kB2 ----------------
__global__ void __launch_bounds__(256) kB1() {
    const int blk = blockIdx.x;          // 256 blocks, 8 trunks each
    const int tid = threadIdx.x;
    const float* src = g_part + (long)blk * 8 * 4096;
#pragma unroll
    for (int i = 0; i < 16; ++i) {
        const int x = tid + i * 256;
        float s = 0.0f;
#pragma unroll
        for (int tt = 0; tt < 8; ++tt) s += src[tt * 4096 + x];
        g_red[blk * 4096 + x] = s;
    }
}
// g_part rows hold M^T => sum over t at x = c*64+e equals S[c][e].
// Store S transposed: g_S[e*64+c] = S[c][e] (natural B rows for kQO GEMM2).
__global__ void __launch_bounds__(256) kB2() {
    const int idx = blockIdx.x * 256 + threadIdx.x;   // idx = c*64 + e
    float s = 0.0f;
#pragma unroll 8
    for (int b = 0; b < B1_BLOCKS; ++b) s += g_red[b * 4096 + idx];
    const int c = idx >> 6, e = idx & 63;
    g_S[e * 64 + c] = s;
}

// ---------------- kQO: mma.sync bf16 hi/lo split (round-10, unchanged) ----------------
#define AH_OFF 0
#define AL_OFF 18432
#define BH_OFF 36864
#define BL_OFF 46080
#define QO_SMEM 55296
#define ASTR 72

__device__ __forceinline__ void gemm_bf16(uint32_t sb, float acc[2][8][4],
                                          int lane, int wid) {
    const uint32_t aRowByte = (uint32_t)((wid * 32 + (lane & 15)) * (ASTR * 2));
    const uint32_t aColByte = (uint32_t)((lane >> 4) * 16);
    const uint32_t bRowByte = (uint32_t)((lane & 7) * (ASTR * 2));
    const uint32_t bColByte = (uint32_t)(((lane >> 3) & 1) * 16);

#pragma unroll
    for (int k0 = 0; k0 < 64; k0 += 16) {
        const uint32_t kByte = (uint32_t)(k0 * 2);
        uint32_t bh[8][2], bl[8][2];
#pragma unroll
        for (int n = 0; n < 8; ++n) {
            const uint32_t ba = sb + BH_OFF + (uint32_t)(n * 8 * ASTR * 2)
                                + bRowByte + kByte + bColByte;
            LDSM_X2(bh[n][0], bh[n][1], ba);
            LDSM_X2(bl[n][0], bl[n][1], ba + (BL_OFF - BH_OFF));
        }
#pragma unroll
        for (int s = 0; s < 2; ++s) {
            const uint32_t aa = sb + AH_OFF + aRowByte + (uint32_t)(s * 16 * ASTR * 2)
                                + kByte + aColByte;
            uint32_t ah[4], al[4];
            LDSM_X4(ah[0], ah[1], ah[2], ah[3], aa);
            LDSM_X4(al[0], al[1], al[2], al[3], aa + (AL_OFF - AH_OFF));
#pragma unroll
            for (int n = 0; n < 8; ++n) {
                MMA16816(acc[s][n], ah, bh[n]);
                MMA16816(acc[s][n], ah, bl[n]);
                MMA16816(acc[s][n], al, bh[n]);
            }
        }
    }
}

__global__ void __launch_bounds__(128, 4) kQO(const float* __restrict__ Qg,
                                              float* __restrict__ outg) {
    extern __shared__ __align__(16) char sm[];
    const uint32_t sb = smem_u32(sm);
    const int tid = threadIdx.x, lane = tid & 31, wid = tid >> 5;
    const long t = blockIdx.x;

    const float4* Q4 = (const float4*)Qg + t * 2048;
#pragma unroll
    for (int i = tid; i < 2048; i += 128) {
        const float4 v = Q4[i];
        const int off = (i >> 4) * (ASTR * 2) + ((i & 15) << 3);
        split_pair(sm + AH_OFF + off,     sm + AL_OFF + off,     v.x, v.y);
        split_pair(sm + AH_OFF + off + 4, sm + AL_OFF + off + 4, v.z, v.w);
    }
    const float4* M4 = (const float4*)g_part + t * 1024;
#pragma unroll
    for (int i = tid; i < 1024; i += 128) {
        const float4 v = M4[i];
        const int off = (i >> 4) * (ASTR * 2) + ((i & 15) << 3);
        split_pair(sm + BH_OFF + off,     sm + BL_OFF + off,     v.x, v.y);
        split_pair(sm + BH_OFF + off + 4, sm + BL_OFF + off + 4, v.z, v.w);
    }
    __syncthreads();

    float acc[2][8][4];
#pragma unroll
    for (int s = 0; s < 2; ++s)
#pragma unroll
        for (int n = 0; n < 8; ++n)
#pragma unroll
            for (int j = 0; j < 4; ++j) acc[s][n][j] = 0.0f;

    gemm_bf16(sb, acc, lane, wid);   // GEMM1: P = Q @ M
    __syncthreads();

    const int g = lane >> 2, tc = lane & 3;
#pragma unroll
    for (int s = 0; s < 2; ++s)
#pragma unroll
        for (int n = 0; n < 8; ++n) {
            const int col = n * 8 + tc * 2;
            const int row1 = wid * 32 + s * 16 + g;
            const int off1 = row1 * (ASTR * 2) + col * 2;
            const int off2 = off1 + 8 * (ASTR * 2);
            split_pair(sm + AH_OFF + off1, sm + AL_OFF + off1,
                       acc[s][n][0], acc[s][n][1]);
            split_pair(sm + AH_OFF + off2, sm + AL_OFF + off2,
                       acc[s][n][2], acc[s][n][3]);
        }
#pragma unroll
    for (int i = tid; i < 1024; i += 128) {
        const float4 v = ((const float4*)g_S)[i];
        const int off = (i >> 4) * (ASTR * 2) + ((i & 15) << 3);
        split_pair(sm + BH_OFF + off,     sm + BL_OFF + off,     v.x, v.y);
        split_pair(sm + BH_OFF + off + 4, sm + BL_OFF + off + 4, v.z, v.w);
    }
    __syncthreads();

#pragma unroll
    for (int s = 0; s < 2; ++s)
#pragma unroll
        for (int n = 0; n < 8; ++n)
#pragma unroll
            for (int j = 0; j < 4; ++j) acc[s][n][j] = 0.0f;

    gemm_bf16(sb, acc, lane, wid);   // GEMM2: out = P @ S

    float* outp = outg + t * (TRUNK * D);
#pragma unroll
    for (int s = 0; s < 2; ++s)
#pragma unroll
        for (int n = 0; n < 8; ++n) {
            const int col = n * 8 + tc * 2;
            const int row1 = wid * 32 + s * 16 + g;
            float2 v0; v0.x = acc[s][n][0]; v0.y = acc[s][n][1];
            float2 v1; v1.x = acc[s][n][2]; v1.y = acc[s][n][3];
            *(float2*)&outp[row1 * 64 + col]       = v0;
            *(float2*)&outp[(row1 + 8) * 64 + col] = v1;
        }
}

extern "C" void kernel_launch(void* const* d_in, const int* in_sizes, int n_in,
                              void* d_out, int out_size) {
    const float* Q = (const float*)d_in[0];
    const float* K = (const float*)d_in[1];
    const float* V = (const float*)d_in[2];
    float* out = (float*)d_out;

    cudaFuncSetAttribute(kA,  cudaFuncAttributeMaxDynamicSharedMemorySize, KA_SMEM);
    cudaFuncSetAttribute(kQO, cudaFuncAttributeMaxDynamicSharedMemorySize, QO_SMEM);

    kA<<<T_TRUNKS, 256, KA_SMEM>>>(K, V);
    kB1<<<B1_BLOCKS, 256>>>();
    kB2<<<16, 256>>>();
    kQO<<<T_TRUNKS, 128, QO_SMEM>>>(Q, out);
}

// round 12
// speedup vs baseline: 1.0925x; 1.0925x over previous
#include <cuda_runtime.h>
#include <cuda_bf16.h>
#include <cstdint>

// LinearAttentionTriton (all-HMMA):
//   g_part_t[e*64+d] = M_t[d][e] = sum_r K[r][d] V[r][e]   -- kA (persistent, bf16 hi/lo HMMA)
//   g_S[e*64+c]      = S[c][e]                              -- kA partials + kB2
//   out_t = (Q_t @ M_t) @ S                                 -- kQO (mma.sync bf16 hi/lo)
// N = 262144, D = 64, TRUNK = 128, T = 2048.

#define D 64
#define TRUNK 128
#define T_TRUNKS 2048
#define GRID_A 444            // 148 SMs * 3 CTAs

__device__ __align__(16) float g_S[D * D];
__device__ __align__(16) float g_part[T_TRUNKS * D * D];
__device__ __align__(16) float g_red[512 * D * D];

// ---------------- common helpers ----------------
__device__ __forceinline__ uint32_t smem_u32(const void* p) {
    uint32_t a;
    asm("{ .reg .u64 t; cvta.to.shared.u64 t, %1; cvt.u32.u64 %0, t; }"
        : "=r"(a) : "l"(p));
    return a;
}
#define LDSM_X4(r0, r1, r2, r3, a) \
    asm volatile("ldmatrix.sync.aligned.m8n8.x4.shared.b16 {%0,%1,%2,%3}, [%4];" \
                 : "=r"(r0), "=r"(r1), "=r"(r2), "=r"(r3) : "r"(a))
#define LDSM_X2(r0, r1, a) \
    asm volatile("ldmatrix.sync.aligned.m8n8.x2.shared.b16 {%0,%1}, [%2];" \
                 : "=r"(r0), "=r"(r1) : "r"(a))
#define LDSM_X4_T(r0, r1, r2, r3, a) \
    asm volatile("ldmatrix.sync.aligned.m8n8.x4.trans.shared.b16 {%0,%1,%2,%3}, [%4];" \
                 : "=r"(r0), "=r"(r1), "=r"(r2), "=r"(r3) : "r"(a))
#define LDSM_X2_T(r0, r1, a) \
    asm volatile("ldmatrix.sync.aligned.m8n8.x2.trans.shared.b16 {%0,%1}, [%2];" \
                 : "=r"(r0), "=r"(r1) : "r"(a))
#define MMA16816(d, a, b) \
    asm volatile("mma.sync.aligned.m16n8k16.row.col.f32.bf16.bf16.f32 " \
                 "{%0,%1,%2,%3}, {%4,%5,%6,%7}, {%8,%9}, {%0,%1,%2,%3};" \
                 : "+f"((d)[0]), "+f"((d)[1]), "+f"((d)[2]), "+f"((d)[3]) \
                 : "r"((a)[0]), "r"((a)[1]), "r"((a)[2]), "r"((a)[3]), \
                   "r"((b)[0]), "r"((b)[1]))

// packed hi/lo split: 2 cvt.bf16x2 + shift/mask + 2 subs per float pair
__device__ __forceinline__ void split_pair(char* ph, char* pl, float x, float y) {
    uint32_t h2;
    asm("cvt.rn.bf16x2.f32 %0, %1, %2;" : "=r"(h2) : "f"(y), "f"(x));  // lo=x, hi=y
    const float fxh = __uint_as_float(h2 << 16);
    const float fyh = __uint_as_float(h2 & 0xffff0000u);
    uint32_t l2;
    asm("cvt.rn.bf16x2.f32 %0, %1, %2;" : "=r"(l2) : "f"(y - fyh), "f"(x - fxh));
    *(uint32_t*)ph = h2;
    *(uint32_t*)pl = l2;
}

// ---------------- kA: persistent, M^T via mma.sync (8 warps: 4m x 2n) ----------------
// out[m=e][n=d] = sum_r V[r][e] K[r][d]  (A = V^T, B = K^T; natural [r][.] storage)
// smem: Kh, Kl, Vh, Vl each [128][72] bf16 = 72 KB -> 3 CTAs/SM.
#define KA_STRB 144
#define KA_KH 0
#define KA_KL 18432
#define KA_VH 36864
#define KA_VL 55296
#define KA_SMEM 73728

__global__ void __launch_bounds__(256) kA(const float* __restrict__ Kg,
                                          const float* __restrict__ Vg) {
    extern __shared__ __align__(16) char sm[];
    const uint32_t sb = smem_u32(sm);
    const int tid = threadIdx.x, lane = tid & 31, wid = tid >> 5;

    const int mt = wid & 3;            // m-tile: rows e = mt*16..+16
    const int nh = wid >> 2;           // n-half: cols d = nh*32..+32
    const int m0 = mt * 16;

    // A (trans x4): lane l -> &V[k + (l&7) + ((l>>4)<<3)][m0 + ((l>>3)&1)*8]
    const uint32_t aBase = sb + KA_VH
        + (uint32_t)(((lane & 7) + ((lane >> 4) << 3)) * KA_STRB)
        + (uint32_t)((m0 + ((lane >> 3) & 1) * 8) * 2);
    // B (trans x2): lane l (0-15) -> &K[k + (l&7) + ((l>>3)&1)*8][n0]
    const uint32_t bBase = sb + KA_KH
        + (uint32_t)(((lane & 7) + ((lane >> 3) & 1) * 8) * KA_STRB)
        + (uint32_t)(nh * 4 * 16);

    float sum[4][4];
#pragma unroll
    for (int n = 0; n < 4; ++n)
#pragma unroll
        for (int j = 0; j < 4; ++j) sum[n][j] = 0.0f;

    const int g = lane >> 2, tc = lane & 3;
    bool first = true;

    for (int t = blockIdx.x; t < T_TRUNKS; t += GRID_A) {
        if (!first) __syncthreads();   // previous iter's smem reads complete
        first = false;

        const float4* K4 = (const float4*)Kg + (long)t * 2048;
        const float4* V4 = (const float4*)Vg + (long)t * 2048;
#pragma unroll
        for (int i = tid; i < 2048; i += 256) {
            const int off = (i >> 4) * KA_STRB + ((i & 15) << 3);
            const float4 kv = K4[i];
            split_pair(sm + KA_KH + off,     sm + KA_KL + off,     kv.x, kv.y);
            split_pair(sm + KA_KH + off + 4, sm + KA_KL + off + 4, kv.z, kv.w);
            const float4 vv = V4[i];
            split_pair(sm + KA_VH + off,     sm + KA_VL + off,     vv.x, vv.y);
            split_pair(sm + KA_VH + off + 4, sm + KA_VL + off + 4, vv.z, vv.w);
        }
        __syncthreads();

        float acc[4][4];
#pragma unroll
        for (int n = 0; n < 4; ++n)
#pragma unroll
            for (int j = 0; j < 4; ++j) acc[n][j] = 0.0f;

#pragma unroll
        for (int k0 = 0; k0 < 128; k0 += 16) {
            uint32_t ah[4], al[4];
            const uint32_t aa = aBase + (uint32_t)(k0 * KA_STRB);
            LDSM_X4_T(ah[0], ah[1], ah[2], ah[3], aa);
            LDSM_X4_T(al[0], al[1], al[2], al[3], aa + (KA_VL - KA_VH));
#pragma unroll
            for (int n = 0; n < 4; ++n) {
                uint32_t bh[2], bl[2];
                const uint32_t ba = bBase + (uint32_t)(k0 * KA_STRB) + (uint32_t)(n * 16);
                LDSM_X2_T(bh[0], bh[1], ba);
                LDSM_X2_T(bl[0], bl[1], ba + (KA_KL - KA_KH));
                MMA16816(acc[n], ah, bh);
                MMA16816(acc[n], ah, bl);
                MMA16816(acc[n], al, bh);
            }
        }

        // write M^T for this trunk + accumulate running S partial
        float* dst = g_part + (long)t * 4096;
#pragma unroll
        for (int n = 0; n < 4; ++n) {
            const int col = nh * 32 + n * 8 + tc * 2;
            float2 v0; v0.x = acc[n][0]; v0.y = acc[n][1];
            float2 v1; v1.x = acc[n][2]; v1.y = acc[n][3];
            *(float2*)&dst[(m0 + g) * 64 + col]     = v0;
            *(float2*)&dst[(m0 + g + 8) * 64 + col] = v1;
#pragma unroll
            for (int j = 0; j < 4; ++j) sum[n][j] += acc[n][j];
        }
    }

    // park this CTA's S partial (layout = M^T rows e, cols d)
    float* red = g_red + (long)blockIdx.x * 4096;
#pragma unroll
    for (int n = 0; n < 4; ++n) {
        const int col = nh * 32 + n * 8 + tc * 2;
        float2 v0; v0.x = sum[n][0]; v0.y = sum[n][1];
        float2 v1; v1.x = sum[n][2]; v1.y = sum[n][3];
        *(float2*)&red[(m0 + g) * 64 + col]     = v0;
        *(float2*)&red[(m0 + g + 8) * 64 + col] = v1;
    }
}

// ---------------- kB2: reduce 444 partials; store S transposed ----------------
// partial rows hold M^T => x = c*64+e sums to S[c][e]; store g_S[e*64+c].
__global__ void __launch_bounds__(256) kB2() {
    const int idx = blockIdx.x * 256 + threadIdx.x;   // idx = c*64 + e
    float s = 0.0f;
    for (int b = 0; b < GRID_A; ++b) s += g_red[(long)b * 4096 + idx];
    const int c = idx >> 6, e = idx & 63;
    g_S[e * 64 + c] = s;
}

// ---------------- kQO: mma.sync bf16 hi/lo split (round-10, unchanged) ----------------
#define AH_OFF 0
#define AL_OFF 18432
#define BH_OFF 36864
#define BL_OFF 46080
#define QO_SMEM 55296
#define ASTR 72

__device__ __forceinline__ void gemm_bf16(uint32_t sb, float acc[2][8][4],
                                          int lane, int wid) {
    const uint32_t aRowByte = (uint32_t)((wid * 32 + (lane & 15)) * (ASTR * 2));
    const uint32_t aColByte = (uint32_t)((lane >> 4) * 16);
    const uint32_t bRowByte = (uint32_t)((lane & 7) * (ASTR * 2));
    const uint32_t bColByte = (uint32_t)(((lane >> 3) & 1) * 16);

#pragma unroll
    for (int k0 = 0; k0 < 64; k0 += 16) {
        const uint32_t kByte = (uint32_t)(k0 * 2);
        uint32_t bh[8][2], bl[8][2];
#pragma unroll
        for (int n = 0; n < 8; ++n) {
            const uint32_t ba = sb + BH_OFF + (uint32_t)(n * 8 * ASTR * 2)
                                + bRowByte + kByte + bColByte;
            LDSM_X2(bh[n][0], bh[n][1], ba);
            LDSM_X2(bl[n][0], bl[n][1], ba + (BL_OFF - BH_OFF));
        }
#pragma unroll
        for (int s = 0; s < 2; ++s) {
            const uint32_t aa = sb + AH_OFF + aRowByte + (uint32_t)(s * 16 * ASTR * 2)
                                + kByte + aColByte;
            uint32_t ah[4], al[4];
            LDSM_X4(ah[0], ah[1], ah[2], ah[3], aa);
            LDSM_X4(al[0], al[1], al[2], al[3], aa + (AL_OFF - AH_OFF));
#pragma unroll
            for (int n = 0; n < 8; ++n) {
                MMA16816(acc[s][n], ah, bh[n]);
                MMA16816(acc[s][n], ah, bl[n]);
                MMA16816(acc[s][n], al, bh[n]);
            }
        }
    }
}

__global__ void __launch_bounds__(128, 4) kQO(const float* __restrict__ Qg,
                                              float* __restrict__ outg) {
    extern __shared__ __align__(16) char sm[];
    const uint32_t sb = smem_u32(sm);
    const int tid = threadIdx.x, lane = tid & 31, wid = tid >> 5;
    const long t = blockIdx.x;

    const float4* Q4 = (const float4*)Qg + t * 2048;
#pragma unroll
    for (int i = tid; i < 2048; i += 128) {
        const float4 v = Q4[i];
        const int off = (i >> 4) * (ASTR * 2) + ((i & 15) << 3);
        split_pair(sm + AH_OFF + off,     sm + AL_OFF + off,     v.x, v.y);
        split_pair(sm + AH_OFF + off + 4, sm + AL_OFF + off + 4, v.z, v.w);
    }
    const float4* M4 = (const float4*)g_part + t * 1024;
#pragma unroll
    for (int i = tid; i < 1024; i += 128) {
        const float4 v = M4[i];
        const int off = (i >> 4) * (ASTR * 2) + ((i & 15) << 3);
        split_pair(sm + BH_OFF + off,     sm + BL_OFF + off,     v.x, v.y);
        split_pair(sm + BH_OFF + off + 4, sm + BL_OFF + off + 4, v.z, v.w);
    }
    __syncthreads();

    float acc[2][8][4];
#pragma unroll
    for (int s = 0; s < 2; ++s)
#pragma unroll
        for (int n = 0; n < 8; ++n)
#pragma unroll
            for (int j = 0; j < 4; ++j) acc[s][n][j] = 0.0f;

    gemm_bf16(sb, acc, lane, wid);   // GEMM1: P = Q @ M
    __syncthreads();

    const int g = lane >> 2, tc = lane & 3;
#pragma unroll
    for (int s = 0; s < 2; ++s)
#pragma unroll
        for (int n = 0; n < 8; ++n) {
            const int col = n * 8 + tc * 2;
            const int row1 = wid * 32 + s * 16 + g;
            const int off1 = row1 * (ASTR * 2) + col * 2;
            const int off2 = off1 + 8 * (ASTR * 2);
            split_pair(sm + AH_OFF + off1, sm + AL_OFF + off1,
                       acc[s][n][0], acc[s][n][1]);
            split_pair(sm + AH_OFF + off2, sm + AL_OFF + off2,
                       acc[s][n][2], acc[s][n][3]);
        }
#pragma unroll
    for (int i = tid; i < 1024; i += 128) {
        const float4 v = ((const float4*)g_S)[i];
        const int off = (i >> 4) * (ASTR * 2) + ((i & 15) << 3);
        split_pair(sm + BH_OFF + off,     sm + BL_OFF + off,     v.x, v.y);
        split_pair(sm + BH_OFF + off + 4, sm + BL_OFF + off + 4, v.z, v.w);
    }
    __syncthreads();

#pragma unroll
    for (int s = 0; s < 2; ++s)
#pragma unroll
        for (int n = 0; n < 8; ++n)
#pragma unroll
            for (int j = 0; j < 4; ++j) acc[s][n][j] = 0.0f;

    gemm_bf16(sb, acc, lane, wid);   // GEMM2: out = P @ S

    float* outp = outg + t * (TRUNK * D);
#pragma unroll
    for (int s = 0; s < 2; ++s)
#pragma unroll
        for (int n = 0; n < 8; ++n) {
            const int col = n * 8 + tc * 2;
            const int row1 = wid * 32 + s * 16 + g;
            float2 v0; v0.x = acc[s][n][0]; v0.y = acc[s][n][1];
            float2 v1; v1.x = acc[s][n][2]; v1.y = acc[s][n][3];
            *(float2*)&outp[row1 * 64 + col]       = v0;
            *(float2*)&outp[(row1 + 8) * 64 + col] = v1;
        }
}

extern "C" void kernel_launch(void* const* d_in, const int* in_sizes, int n_in,
                              void* d_out, int out_size) {
    const float* Q = (const float*)d_in[0];
    const float* K = (const float*)d_in[1];
    const float* V = (const float*)d_in[2];
    float* out = (float*)d_out;

    cudaFuncSetAttribute(kA,  cudaFuncAttributeMaxDynamicSharedMemorySize, KA_SMEM);
    cudaFuncSetAttribute(kQO, cudaFuncAttributeMaxDynamicSharedMemorySize, QO_SMEM);

    kA<<<GRID_A, 256, KA_SMEM>>>(K, V);
    kB2<<<16, 256>>>();
    kQO<<<T_TRUNKS, 128, QO_SMEM>>>(Q, out);
}